// round 1
// baseline (speedup 1.0000x reference)
#include <cuda_runtime.h>

#define D_IN   1024
#define D_OUTD 1024
#define NTREES 12
#define NINT   7
#define NCOL   96      // 84 decision cols + 12 gate cols
#define NHEADS 3
#define MAX_TOK 8192

// scratch: per-token combined coefficients c[tok][t*8 + l]
__device__ float g_coef[MAX_TOK * NCOL];

// ---------------------------------------------------------------------------
// Kernel 1: routing GEMM [TM1 x 96 x 1024] + sigmoid / leaf products / softmax
// ---------------------------------------------------------------------------
#define TM1  32
#define KC1  128
#define T1   128
#define XROW (KC1 + 4)   // 132 floats, keeps float4 alignment, breaks bank period

__global__ __launch_bounds__(T1) void k1_route(
    const float* __restrict__ x,
    const float* __restrict__ dw,
    const float* __restrict__ db,
    const float* __restrict__ ntl,
    const float* __restrict__ gw,
    const float* __restrict__ gb)
{
    extern __shared__ float sm[];
    float* Xs    = sm;                     // TM1 * XROW
    float* Ws    = sm + TM1 * XROW;        // NCOL * XROW
    float* sInvT = Ws + NCOL * XROW;       // 84
    float* sBias = sInvT + 84;             // 84
    float* sGb   = sBias + 84;             // 12
    float* Ds    = Ws;                     // epilogue overlay: TM1 x 100

    const int tid = threadIdx.x;
    const int tokbase = blockIdx.x * TM1;

    if (tid < 84) {
        float z = ntl[tid] + 0.5413f;
        float sp = (z > 15.f) ? z : log1pf(__expf(z));   // softplus, TEMPERATURE=1
        sInvT[tid] = 1.0f / sp;
        sBias[tid] = db[tid];
    } else if (tid >= 96 && tid < 96 + NTREES) {
        sGb[tid - 96] = gb[tid - 96];
    }

    const int ng = tid & 15;   // 16 groups x 6 cols
    const int tg = tid >> 4;   // 8 groups x 4 tokens

    float acc[4][6];
#pragma unroll
    for (int i = 0; i < 4; i++)
#pragma unroll
        for (int j = 0; j < 6; j++) acc[i][j] = 0.f;

    for (int kb = 0; kb < D_IN; kb += KC1) {
        __syncthreads();
#pragma unroll
        for (int i = 0; i < (TM1 * KC1 / 4) / T1; i++) {   // 8
            int idx = i * T1 + tid;
            int c4 = idx & 31;
            int r  = idx >> 5;
            *(float4*)&Xs[r * XROW + 4 * c4] =
                *(const float4*)&x[(size_t)(tokbase + r) * D_IN + kb + 4 * c4];
        }
#pragma unroll
        for (int i = 0; i < (NCOL * KC1 / 4) / T1; i++) {  // 24
            int idx = i * T1 + tid;
            int c4 = idx & 31;
            int r  = idx >> 5;
            const float* src = (r < 84) ? (dw + (size_t)r * D_IN)
                                        : (gw + (size_t)(r - 84) * D_IN);
            *(float4*)&Ws[r * XROW + 4 * c4] = *(const float4*)&src[kb + 4 * c4];
        }
        __syncthreads();

#pragma unroll 4
        for (int k4 = 0; k4 < KC1 / 4; k4++) {
            float4 xv[4], wv[6];
#pragma unroll
            for (int i = 0; i < 4; i++)
                xv[i] = *(const float4*)&Xs[(4 * tg + i) * XROW + 4 * k4];
#pragma unroll
            for (int j = 0; j < 6; j++)
                wv[j] = *(const float4*)&Ws[(6 * ng + j) * XROW + 4 * k4];
#pragma unroll
            for (int i = 0; i < 4; i++)
#pragma unroll
                for (int j = 0; j < 6; j++) {
                    acc[i][j] += xv[i].x * wv[j].x;
                    acc[i][j] += xv[i].y * wv[j].y;
                    acc[i][j] += xv[i].z * wv[j].z;
                    acc[i][j] += xv[i].w * wv[j].w;
                }
        }
    }
    __syncthreads();
#pragma unroll
    for (int i = 0; i < 4; i++)
#pragma unroll
        for (int j = 0; j < 6; j++)
            Ds[(4 * tg + i) * 100 + 6 * ng + j] = acc[i][j];
    __syncthreads();

    if (tid < TM1) {
        const float* d = &Ds[tid * 100];
        // gate softmax over trees
        float g[NTREES];
        float m = -1e30f;
#pragma unroll
        for (int t = 0; t < NTREES; t++) { g[t] = d[84 + t] + sGb[t]; m = fmaxf(m, g[t]); }
        float s = 0.f;
#pragma unroll
        for (int t = 0; t < NTREES; t++) { g[t] = __expf(g[t] - m); s += g[t]; }
        float inv = 1.0f / s;

        float* orow = &g_coef[(size_t)(tokbase + tid) * NCOL];
#pragma unroll
        for (int t = 0; t < NTREES; t++) {
            float w = g[t] * inv;
            float p[NINT];
#pragma unroll
            for (int n = 0; n < NINT; n++) {
                float z = (d[t * 7 + n] + sBias[t * 7 + n]) * sInvT[t * 7 + n];
                p[n] = 1.0f / (1.0f + __expf(-z));
            }
            // leaf l = b0*4 + b1*2 + b2; nodes: 0, 1+b0, 3+2*b0+b1; factor = b? (1-p):p
            float a0 = p[0], a1 = 1.f - p[0];
            orow[t * 8 + 0] = w * a0 * p[1] * p[3];
            orow[t * 8 + 1] = w * a0 * p[1] * (1.f - p[3]);
            orow[t * 8 + 2] = w * a0 * (1.f - p[1]) * p[4];
            orow[t * 8 + 3] = w * a0 * (1.f - p[1]) * (1.f - p[4]);
            orow[t * 8 + 4] = w * a1 * p[2] * p[5];
            orow[t * 8 + 5] = w * a1 * p[2] * (1.f - p[5]);
            orow[t * 8 + 6] = w * a1 * (1.f - p[2]) * p[6];
            orow[t * 8 + 7] = w * a1 * (1.f - p[2]) * (1.f - p[6]);
        }
    }
}

// ---------------------------------------------------------------------------
// Kernel 2: out[h,tok,d] = sum_j c[tok,j] * LO[h,j,d]   (f32x2 packed FFMA)
// ---------------------------------------------------------------------------
#define TM2 64
#define DN2 128
#define T2  256

__global__ __launch_bounds__(T2) void k2_combine(
    const float* __restrict__ lo, float* __restrict__ out, int ntok)
{
    extern __shared__ float sm[];
    float* LOs = sm;               // NCOL * DN2
    float* Cs  = sm + NCOL * DN2;  // TM2 * NCOL

    const int tid = threadIdx.x;
    const int tokbase = blockIdx.x * TM2;
    const int dbase = blockIdx.y * DN2;
    const int h = blockIdx.z;

    const float* losrc = lo + (size_t)h * NCOL * D_OUTD + dbase;
#pragma unroll
    for (int i = 0; i < (NCOL * DN2 / 4) / T2; i++) {   // 12
        int idx = i * T2 + tid;
        int c4 = idx & 31;       // DN2/4 = 32
        int r  = idx >> 5;
        *(float4*)&LOs[r * DN2 + 4 * c4] =
            *(const float4*)&losrc[(size_t)r * D_OUTD + 4 * c4];
    }
#pragma unroll
    for (int i = 0; i < (TM2 * NCOL / 4) / T2; i++) {   // 6
        int idx = i * T2 + tid;
        int c4 = idx % 24;       // NCOL/4
        int r  = idx / 24;
        *(float4*)&Cs[r * NCOL + 4 * c4] =
            *(const float4*)&g_coef[(size_t)(tokbase + r) * NCOL + 4 * c4];
    }
    __syncthreads();

    const int dg = tid & 15;     // 16 groups x 8 d
    const int tg = tid >> 4;     // 16 groups x 4 tok
    const int d0 = dg * 8;

    unsigned long long acc[4][4];
#pragma unroll
    for (int i = 0; i < 4; i++)
#pragma unroll
        for (int j = 0; j < 4; j++) acc[i][j] = 0ull;   // bits of (0.f, 0.f)

    for (int j4 = 0; j4 < NCOL / 4; j4++) {
        float4 cv[4];
#pragma unroll
        for (int i = 0; i < 4; i++)
            cv[i] = *(const float4*)&Cs[(4 * tg + i) * NCOL + 4 * j4];
#pragma unroll
        for (int jj = 0; jj < 4; jj++) {
            int j = 4 * j4 + jj;
            ulonglong2 l0 = *(const ulonglong2*)&LOs[j * DN2 + d0];
            ulonglong2 l1 = *(const ulonglong2*)&LOs[j * DN2 + d0 + 4];
#pragma unroll
            for (int i = 0; i < 4; i++) {
                float cf = (jj == 0) ? cv[i].x : (jj == 1) ? cv[i].y
                         : (jj == 2) ? cv[i].z : cv[i].w;
                unsigned cu = __float_as_uint(cf);
                unsigned long long cd;
                asm("mov.b64 %0, {%1,%1};" : "=l"(cd) : "r"(cu));
                asm("fma.rn.f32x2 %0, %1, %2, %0;" : "+l"(acc[i][0]) : "l"(l0.x), "l"(cd));
                asm("fma.rn.f32x2 %0, %1, %2, %0;" : "+l"(acc[i][1]) : "l"(l0.y), "l"(cd));
                asm("fma.rn.f32x2 %0, %1, %2, %0;" : "+l"(acc[i][2]) : "l"(l1.x), "l"(cd));
                asm("fma.rn.f32x2 %0, %1, %2, %0;" : "+l"(acc[i][3]) : "l"(l1.y), "l"(cd));
            }
        }
    }

#pragma unroll
    for (int i = 0; i < 4; i++) {
        size_t tok = (size_t)tokbase + 4 * tg + i;
        float* o = out + ((size_t)h * ntok + tok) * D_OUTD + dbase + d0;
        ulonglong2 v0; v0.x = acc[i][0]; v0.y = acc[i][1];
        ulonglong2 v1; v1.x = acc[i][2]; v1.y = acc[i][3];
        *(ulonglong2*)&o[0] = v0;
        *(ulonglong2*)&o[4] = v1;
    }
}

// ---------------------------------------------------------------------------
extern "C" void kernel_launch(void* const* d_in, const int* in_sizes, int n_in,
                              void* d_out, int out_size)
{
    const float* x   = (const float*)d_in[0];
    const float* dw  = (const float*)d_in[1];
    const float* db  = (const float*)d_in[2];
    const float* ntl = (const float*)d_in[3];
    const float* lo  = (const float*)d_in[4];
    const float* gw  = (const float*)d_in[5];
    const float* gb  = (const float*)d_in[6];
    float* out = (float*)d_out;

    int ntok = in_sizes[0] / D_IN;   // 8192

    int smem1 = (TM1 * XROW + NCOL * XROW + 84 + 84 + 12) * (int)sizeof(float); // ~68 KB
    int smem2 = (NCOL * DN2 + TM2 * NCOL) * (int)sizeof(float);                 // 72 KB
    cudaFuncSetAttribute(k1_route,   cudaFuncAttributeMaxDynamicSharedMemorySize, smem1);
    cudaFuncSetAttribute(k2_combine, cudaFuncAttributeMaxDynamicSharedMemorySize, smem2);

    k1_route<<<ntok / TM1, T1, smem1>>>(x, dw, db, ntl, gw, gb);

    dim3 g2(ntok / TM2, D_OUTD / DN2, NHEADS);
    k2_combine<<<g2, T2, smem2>>>(lo, out, ntok);
}

// round 2
// speedup vs baseline: 1.4960x; 1.4960x over previous
#include <cuda_runtime.h>

#define D_IN   1024
#define D_OUTD 1024
#define NTREES 12
#define NINT   7
#define NCOL   96      // 84 decision cols + 12 gate cols
#define NHEADS 3
#define MAX_TOK 8192

// scratch: combined coefficients, TRANSPOSED: g_coef[j][tok], j = tree*8 + leaf
__device__ float g_coef[NCOL * MAX_TOK];

__device__ __forceinline__ void fma2(unsigned long long& acc,
                                     unsigned long long a, unsigned long long b) {
    asm("fma.rn.f32x2 %0, %1, %2, %0;" : "+l"(acc) : "l"(a), "l"(b));
}
__device__ __forceinline__ unsigned long long dup2(float f) {
    unsigned long long d; unsigned u = __float_as_uint(f);
    asm("mov.b64 %0, {%1,%1};" : "=l"(d) : "r"(u));
    return d;
}
__device__ __forceinline__ float2 unpack2(unsigned long long v) {
    float2 r;
    asm("mov.b64 {%0,%1}, %2;" : "=f"(r.x), "=f"(r.y) : "l"(v));
    return r;
}

// ---------------------------------------------------------------------------
// Kernel 1: routing GEMM [32 tok x 96 col x 1024] + sigmoid/leaf/softmax
// ---------------------------------------------------------------------------
#define TM1  32
#define KC1  128
#define T1   128
#define XROW (KC1 + 4)   // 132 floats; col stride 132*4=528B = 33*16B (odd) -> conflict-free

__global__ __launch_bounds__(T1) void k1_route(
    const float* __restrict__ x,
    const float* __restrict__ dw,
    const float* __restrict__ db,
    const float* __restrict__ ntl,
    const float* __restrict__ gw,
    const float* __restrict__ gb,
    int ntok)
{
    extern __shared__ float sm[];
    float* Xs    = sm;                     // TM1 * XROW
    float* Ws    = sm + TM1 * XROW;        // NCOL * XROW
    float* sInvT = Ws + NCOL * XROW;       // 84
    float* sBias = sInvT + 84;             // 84
    float* sGb   = sBias + 84;             // 12
    float* Ds    = Ws;                     // epilogue overlay: TM1 x 100

    const int tid = threadIdx.x;
    const int tokbase = blockIdx.x * TM1;

    if (tid < 84) {
        float z = ntl[tid] + 0.5413f;
        float sp = (z > 15.f) ? z : log1pf(__expf(z));   // softplus, TEMPERATURE=1
        sInvT[tid] = 1.0f / sp;
        sBias[tid] = db[tid];
    } else if (tid >= 96 && tid < 96 + NTREES) {
        sGb[tid - 96] = gb[tid - 96];
    }

    const int ng = tid & 15;   // col base: cols ng + 16*j, j=0..5
    const int tg = tid >> 4;   // 8 groups x 4 tokens

    unsigned long long acc[4][6];
#pragma unroll
    for (int i = 0; i < 4; i++)
#pragma unroll
        for (int j = 0; j < 6; j++) acc[i][j] = 0ull;

    for (int kb = 0; kb < D_IN; kb += KC1) {
        __syncthreads();
#pragma unroll
        for (int i = 0; i < (TM1 * KC1 / 4) / T1; i++) {   // 8
            int idx = i * T1 + tid;
            int c4 = idx & 31;
            int r  = idx >> 5;
            *(float4*)&Xs[r * XROW + 4 * c4] =
                *(const float4*)&x[(size_t)(tokbase + r) * D_IN + kb + 4 * c4];
        }
#pragma unroll
        for (int i = 0; i < (NCOL * KC1 / 4) / T1; i++) {  // 24
            int idx = i * T1 + tid;
            int c4 = idx & 31;
            int r  = idx >> 5;
            const float* src = (r < 84) ? (dw + (size_t)r * D_IN)
                                        : (gw + (size_t)(r - 84) * D_IN);
            *(float4*)&Ws[r * XROW + 4 * c4] = *(const float4*)&src[kb + 4 * c4];
        }
        __syncthreads();

#pragma unroll 2
        for (int k4 = 0; k4 < KC1 / 4; k4++) {
            ulonglong2 xv[4], wv[6];
#pragma unroll
            for (int i = 0; i < 4; i++)
                xv[i] = *(const ulonglong2*)&Xs[(4 * tg + i) * XROW + 4 * k4];
#pragma unroll
            for (int j = 0; j < 6; j++)
                wv[j] = *(const ulonglong2*)&Ws[(ng + 16 * j) * XROW + 4 * k4];
#pragma unroll
            for (int i = 0; i < 4; i++)
#pragma unroll
                for (int j = 0; j < 6; j++) {
                    fma2(acc[i][j], xv[i].x, wv[j].x);
                    fma2(acc[i][j], xv[i].y, wv[j].y);
                }
        }
    }
    __syncthreads();
#pragma unroll
    for (int i = 0; i < 4; i++)
#pragma unroll
        for (int j = 0; j < 6; j++) {
            float2 p = unpack2(acc[i][j]);
            Ds[(4 * tg + i) * 100 + ng + 16 * j] = p.x + p.y;
        }
    __syncthreads();

    if (tid < TM1) {
        const float* d = &Ds[tid * 100];
        // gate softmax over trees
        float g[NTREES];
        float m = -1e30f;
#pragma unroll
        for (int t = 0; t < NTREES; t++) { g[t] = d[84 + t] + sGb[t]; m = fmaxf(m, g[t]); }
        float s = 0.f;
#pragma unroll
        for (int t = 0; t < NTREES; t++) { g[t] = __expf(g[t] - m); s += g[t]; }
        float inv = 1.0f / s;

        const int tok = tokbase + tid;
#pragma unroll
        for (int t = 0; t < NTREES; t++) {
            float w = g[t] * inv;
            float p[NINT];
#pragma unroll
            for (int n = 0; n < NINT; n++) {
                float z = (d[t * 7 + n] + sBias[t * 7 + n]) * sInvT[t * 7 + n];
                p[n] = 1.0f / (1.0f + __expf(-z));
            }
            float a0 = p[0], a1 = 1.f - p[0];
            float v[8];
            v[0] = w * a0 * p[1] * p[3];
            v[1] = w * a0 * p[1] * (1.f - p[3]);
            v[2] = w * a0 * (1.f - p[1]) * p[4];
            v[3] = w * a0 * (1.f - p[1]) * (1.f - p[4]);
            v[4] = w * a1 * p[2] * p[5];
            v[5] = w * a1 * p[2] * (1.f - p[5]);
            v[6] = w * a1 * (1.f - p[2]) * p[6];
            v[7] = w * a1 * (1.f - p[2]) * (1.f - p[6]);
#pragma unroll
            for (int l = 0; l < 8; l++)
                g_coef[(size_t)(t * 8 + l) * ntok + tok] = v[l];   // coalesced across tid
        }
    }
}

// ---------------------------------------------------------------------------
// Kernel 2: out[h,tok,d] = sum_j c[j,tok] * LO[h,j,d]
//   per warp: 16 tokens x 128 d; per lane: 16 tok x 4 d (f32x2 accumulators)
//   LO reads: 512B contiguous per warp (conflict-free); C reads: broadcast
// ---------------------------------------------------------------------------
#define TM2 128
#define DN2 128
#define T2  256

__global__ __launch_bounds__(T2, 2) void k2_combine(
    const float* __restrict__ lo, float* __restrict__ out, int ntok)
{
    extern __shared__ float sm[];
    float* LOs = sm;               // NCOL * DN2  (48KB)
    float* Cs  = sm + NCOL * DN2;  // NCOL * TM2  (48KB), layout [j][tok]

    const int tid = threadIdx.x;
    const int lane = tid & 31;
    const int w = tid >> 5;        // 8 warps, each owns 16 tokens
    const int tokbase = blockIdx.x * TM2;
    const int dbase = blockIdx.y * DN2;
    const int h = blockIdx.z;

    const float* losrc = lo + (size_t)h * NCOL * D_OUTD + dbase;
#pragma unroll
    for (int i = 0; i < (NCOL * DN2 / 4) / T2; i++) {   // 12
        int idx = i * T2 + tid;
        int c4 = idx & 31;       // DN2/4 = 32
        int r  = idx >> 5;
        *(float4*)&LOs[r * DN2 + 4 * c4] =
            *(const float4*)&losrc[(size_t)r * D_OUTD + 4 * c4];
    }
#pragma unroll
    for (int i = 0; i < (NCOL * TM2 / 4) / T2; i++) {   // 12
        int idx = i * T2 + tid;
        int c4 = idx & 31;       // TM2/4 = 32
        int r  = idx >> 5;
        *(float4*)&Cs[r * TM2 + 4 * c4] =
            *(const float4*)&g_coef[(size_t)r * ntok + tokbase + 4 * c4];
    }
    __syncthreads();

    const int d0 = lane * 4;       // 4 consecutive floats per lane
    const int t0 = w * 16;         // 16 tokens per warp

    unsigned long long acc[16][2];
#pragma unroll
    for (int i = 0; i < 16; i++) { acc[i][0] = 0ull; acc[i][1] = 0ull; }

#pragma unroll 4
    for (int j = 0; j < NCOL; j++) {
        ulonglong2 lv = *(const ulonglong2*)&LOs[j * DN2 + d0];
        float4 c0 = *(const float4*)&Cs[j * TM2 + t0 + 0];
        float4 c1 = *(const float4*)&Cs[j * TM2 + t0 + 4];
        float4 c2 = *(const float4*)&Cs[j * TM2 + t0 + 8];
        float4 c3 = *(const float4*)&Cs[j * TM2 + t0 + 12];
        float cf[16] = {c0.x, c0.y, c0.z, c0.w, c1.x, c1.y, c1.z, c1.w,
                        c2.x, c2.y, c2.z, c2.w, c3.x, c3.y, c3.z, c3.w};
#pragma unroll
        for (int i = 0; i < 16; i++) {
            unsigned long long cd = dup2(cf[i]);
            fma2(acc[i][0], lv.x, cd);
            fma2(acc[i][1], lv.y, cd);
        }
    }

#pragma unroll
    for (int i = 0; i < 16; i++) {
        size_t tok = (size_t)tokbase + t0 + i;
        float* o = out + ((size_t)h * ntok + tok) * D_OUTD + dbase + d0;
        ulonglong2 v; v.x = acc[i][0]; v.y = acc[i][1];
        *(ulonglong2*)o = v;
    }
}

// ---------------------------------------------------------------------------
extern "C" void kernel_launch(void* const* d_in, const int* in_sizes, int n_in,
                              void* d_out, int out_size)
{
    const float* x   = (const float*)d_in[0];
    const float* dw  = (const float*)d_in[1];
    const float* db  = (const float*)d_in[2];
    const float* ntl = (const float*)d_in[3];
    const float* lo  = (const float*)d_in[4];
    const float* gw  = (const float*)d_in[5];
    const float* gb  = (const float*)d_in[6];
    float* out = (float*)d_out;

    int ntok = in_sizes[0] / D_IN;   // 8192

    int smem1 = (TM1 * XROW + NCOL * XROW + 84 + 84 + 12) * (int)sizeof(float); // ~68 KB
    int smem2 = (NCOL * DN2 + NCOL * TM2) * (int)sizeof(float);                 // 96 KB
    cudaFuncSetAttribute(k1_route,   cudaFuncAttributeMaxDynamicSharedMemorySize, smem1);
    cudaFuncSetAttribute(k2_combine, cudaFuncAttributeMaxDynamicSharedMemorySize, smem2);

    k1_route<<<ntok / TM1, T1, smem1>>>(x, dw, db, ntl, gw, gb, ntok);

    dim3 g2(ntok / TM2, D_OUTD / DN2, NHEADS);
    k2_combine<<<g2, T2, smem2>>>(lo, out, ntok);
}

// round 4
// speedup vs baseline: 2.3337x; 1.5600x over previous
#include <cuda_runtime.h>
#include <cstdint>

#define D_IN   1024
#define D_OUTD 1024
#define NTREES 12
#define NINT   7
#define NCOL   96      // 84 decision cols + 12 gate cols; also 12 trees * 8 leaves
#define NHEADS 3
#define MAX_TOK 8192

// scratch
__device__ float g_coef[MAX_TOK * NCOL];          // [tok][j]  (A operand, K-major)
__device__ float g_lot[NHEADS * D_OUTD * NCOL];   // [h][d][j] (B operand, K-major, tf32-rounded)

__device__ __forceinline__ void fma2(unsigned long long& acc,
                                     unsigned long long a, unsigned long long b) {
    asm("fma.rn.f32x2 %0, %1, %2, %0;" : "+l"(acc) : "l"(a), "l"(b));
}
__device__ __forceinline__ float2 unpack2(unsigned long long v) {
    float2 r;
    asm("mov.b64 {%0,%1}, %2;" : "=f"(r.x), "=f"(r.y) : "l"(v));
    return r;
}
__device__ __forceinline__ uint32_t cvt_tf32(float f) {
    uint32_t u;
    asm("cvt.rna.tf32.f32 %0, %1;" : "=r"(u) : "f"(f));
    return u;
}

// ---------------------------------------------------------------------------
// Kernel 0: LO transpose [h][j][d] -> [h][d][j] with tf32 rounding
// ---------------------------------------------------------------------------
__global__ void k0_transpose(const float* __restrict__ lo)
{
    __shared__ float t[32][33];
    const int h = blockIdx.z, j0 = blockIdx.y * 32, d0 = blockIdx.x * 32;
    const int tx = threadIdx.x, ty = threadIdx.y;   // 32 x 8
#pragma unroll
    for (int i = 0; i < 32; i += 8)
        t[ty + i][tx] = lo[((size_t)h * NCOL + (j0 + ty + i)) * D_OUTD + d0 + tx];
    __syncthreads();
#pragma unroll
    for (int i = 0; i < 32; i += 8) {
        uint32_t u = cvt_tf32(t[tx][ty + i]);
        g_lot[((size_t)h * D_OUTD + (d0 + ty + i)) * NCOL + j0 + tx] = __uint_as_float(u);
    }
}

// ---------------------------------------------------------------------------
// Kernel 1: routing GEMM [32 tok x 96 col x 1024] + sigmoid/leaf/softmax
// ---------------------------------------------------------------------------
#define TM1  32
#define KC1  128
#define T1   128
#define XROW (KC1 + 4)

__global__ __launch_bounds__(T1) void k1_route(
    const float* __restrict__ x,
    const float* __restrict__ dw,
    const float* __restrict__ db,
    const float* __restrict__ ntl,
    const float* __restrict__ gw,
    const float* __restrict__ gb,
    int ntok)
{
    extern __shared__ float sm[];
    float* Xs    = sm;                     // TM1 * XROW
    float* Ws    = sm + TM1 * XROW;        // NCOL * XROW
    float* sInvT = Ws + NCOL * XROW;       // 84
    float* sBias = sInvT + 84;             // 84
    float* sGb   = sBias + 84;             // 12
    float* Ds    = Ws;                     // epilogue overlay: TM1 x 100

    const int tid = threadIdx.x;
    const int tokbase = blockIdx.x * TM1;

    if (tid < 84) {
        float z = ntl[tid] + 0.5413f;
        float sp = (z > 15.f) ? z : log1pf(__expf(z));
        sInvT[tid] = 1.0f / sp;
        sBias[tid] = db[tid];
    } else if (tid >= 96 && tid < 96 + NTREES) {
        sGb[tid - 96] = gb[tid - 96];
    }

    const int ng = tid & 15;
    const int tg = tid >> 4;

    unsigned long long acc[4][6];
#pragma unroll
    for (int i = 0; i < 4; i++)
#pragma unroll
        for (int j = 0; j < 6; j++) acc[i][j] = 0ull;

    for (int kb = 0; kb < D_IN; kb += KC1) {
        __syncthreads();
#pragma unroll
        for (int i = 0; i < (TM1 * KC1 / 4) / T1; i++) {
            int idx = i * T1 + tid;
            int c4 = idx & 31;
            int r  = idx >> 5;
            *(float4*)&Xs[r * XROW + 4 * c4] =
                *(const float4*)&x[(size_t)(tokbase + r) * D_IN + kb + 4 * c4];
        }
#pragma unroll
        for (int i = 0; i < (NCOL * KC1 / 4) / T1; i++) {
            int idx = i * T1 + tid;
            int c4 = idx & 31;
            int r  = idx >> 5;
            const float* src = (r < 84) ? (dw + (size_t)r * D_IN)
                                        : (gw + (size_t)(r - 84) * D_IN);
            *(float4*)&Ws[r * XROW + 4 * c4] = *(const float4*)&src[kb + 4 * c4];
        }
        __syncthreads();

#pragma unroll 2
        for (int k4 = 0; k4 < KC1 / 4; k4++) {
            ulonglong2 xv[4], wv[6];
#pragma unroll
            for (int i = 0; i < 4; i++)
                xv[i] = *(const ulonglong2*)&Xs[(4 * tg + i) * XROW + 4 * k4];
#pragma unroll
            for (int j = 0; j < 6; j++)
                wv[j] = *(const ulonglong2*)&Ws[(ng + 16 * j) * XROW + 4 * k4];
#pragma unroll
            for (int i = 0; i < 4; i++)
#pragma unroll
                for (int j = 0; j < 6; j++) {
                    fma2(acc[i][j], xv[i].x, wv[j].x);
                    fma2(acc[i][j], xv[i].y, wv[j].y);
                }
        }
    }
    __syncthreads();
#pragma unroll
    for (int i = 0; i < 4; i++)
#pragma unroll
        for (int j = 0; j < 6; j++) {
            float2 p = unpack2(acc[i][j]);
            Ds[(4 * tg + i) * 100 + ng + 16 * j] = p.x + p.y;
        }
    __syncthreads();

    if (tid < TM1) {
        const float* d = &Ds[tid * 100];
        float g[NTREES];
        float m = -1e30f;
#pragma unroll
        for (int t = 0; t < NTREES; t++) { g[t] = d[84 + t] + sGb[t]; m = fmaxf(m, g[t]); }
        float s = 0.f;
#pragma unroll
        for (int t = 0; t < NTREES; t++) { g[t] = __expf(g[t] - m); s += g[t]; }
        float inv = 1.0f / s;

        const int tok = tokbase + tid;
        float* orow = &g_coef[(size_t)tok * NCOL];
#pragma unroll
        for (int t = 0; t < NTREES; t++) {
            float w = g[t] * inv;
            float p[NINT];
#pragma unroll
            for (int n = 0; n < NINT; n++) {
                float z = (d[t * 7 + n] + sBias[t * 7 + n]) * sInvT[t * 7 + n];
                p[n] = 1.0f / (1.0f + __expf(-z));
            }
            float a0 = p[0], a1 = 1.f - p[0];
            float4 v0, v1;
            v0.x = w * a0 * p[1] * p[3];
            v0.y = w * a0 * p[1] * (1.f - p[3]);
            v0.z = w * a0 * (1.f - p[1]) * p[4];
            v0.w = w * a0 * (1.f - p[1]) * (1.f - p[4]);
            v1.x = w * a1 * p[2] * p[5];
            v1.y = w * a1 * p[2] * (1.f - p[5]);
            v1.z = w * a1 * (1.f - p[2]) * p[6];
            v1.w = w * a1 * (1.f - p[2]) * (1.f - p[6]);
            *(float4*)&orow[t * 8 + 0] = v0;
            *(float4*)&orow[t * 8 + 4] = v1;
        }
    }
}

// ---------------------------------------------------------------------------
// Kernel 2: mma.sync tf32 GEMM. Per CTA: D[128 tok x 128 d] = A[128x96] B^T
//   A = g_coef tile (cvt->tf32 during staging), B = g_lot tile (pre-rounded)
//   smem row stride 100 floats -> conflict-free fragment loads
//   8 warps: 2 (m) x 4 (n); warp tile 64x32 = 4x4 m16n8k8 tiles
// ---------------------------------------------------------------------------
#define T2 256
#define SROW 100
#define SMEM2 (2 * 128 * SROW * 4)

__global__ __launch_bounds__(T2, 2) void k2_mma(float* __restrict__ out, int ntok)
{
    extern __shared__ float sm2[];
    float* As = sm2;                 // 128 x SROW
    float* Bs = sm2 + 128 * SROW;    // 128 x SROW

    const int tid = threadIdx.x;
    const int tokbase = blockIdx.x * 128;
    const int dbase   = blockIdx.y * 128;
    const int h       = blockIdx.z;

    // stage A with tf32 rounding
#pragma unroll
    for (int i = 0; i < 12; i++) {
        int idx = i * T2 + tid;
        int row = idx / 24, c4 = idx % 24;
        float4 v = *(const float4*)&g_coef[(size_t)(tokbase + row) * NCOL + 4 * c4];
        float4 w;
        w.x = __uint_as_float(cvt_tf32(v.x));
        w.y = __uint_as_float(cvt_tf32(v.y));
        w.z = __uint_as_float(cvt_tf32(v.z));
        w.w = __uint_as_float(cvt_tf32(v.w));
        *(float4*)&As[row * SROW + 4 * c4] = w;
    }
    // stage B (already tf32-rounded)
    const float* bsrc = g_lot + ((size_t)h * D_OUTD + dbase) * NCOL;
#pragma unroll
    for (int i = 0; i < 12; i++) {
        int idx = i * T2 + tid;
        int row = idx / 24, c4 = idx % 24;
        *(float4*)&Bs[row * SROW + 4 * c4] =
            *(const float4*)&bsrc[(size_t)row * NCOL + 4 * c4];
    }
    __syncthreads();

    const int lane = tid & 31, wid = tid >> 5;
    const int m0 = (wid >> 2) * 64;      // 2 warps in m
    const int n0 = (wid & 3) * 32;       // 4 warps in n
    const int r = lane >> 2, c = lane & 3;

    float acc[4][4][4];
#pragma unroll
    for (int tm = 0; tm < 4; tm++)
#pragma unroll
        for (int tn = 0; tn < 4; tn++)
#pragma unroll
            for (int q = 0; q < 4; q++) acc[tm][tn][q] = 0.f;

#pragma unroll
    for (int ks = 0; ks < 12; ks++) {
        const int k0 = ks * 8;
        uint32_t a[4][4], b[4][2];
#pragma unroll
        for (int tm = 0; tm < 4; tm++) {
            const uint32_t* ap = (const uint32_t*)&As[(m0 + tm * 16 + r) * SROW + k0 + c];
            a[tm][0] = ap[0];
            a[tm][1] = ap[8 * SROW];
            a[tm][2] = ap[4];
            a[tm][3] = ap[8 * SROW + 4];
        }
#pragma unroll
        for (int tn = 0; tn < 4; tn++) {
            const uint32_t* bp = (const uint32_t*)&Bs[(n0 + tn * 8 + r) * SROW + k0 + c];
            b[tn][0] = bp[0];
            b[tn][1] = bp[4];
        }
#pragma unroll
        for (int tm = 0; tm < 4; tm++)
#pragma unroll
            for (int tn = 0; tn < 4; tn++) {
                asm("mma.sync.aligned.m16n8k8.row.col.f32.tf32.tf32.f32 "
                    "{%0,%1,%2,%3}, {%4,%5,%6,%7}, {%8,%9}, {%0,%1,%2,%3};"
                    : "+f"(acc[tm][tn][0]), "+f"(acc[tm][tn][1]),
                      "+f"(acc[tm][tn][2]), "+f"(acc[tm][tn][3])
                    : "r"(a[tm][0]), "r"(a[tm][1]), "r"(a[tm][2]), "r"(a[tm][3]),
                      "r"(b[tn][0]), "r"(b[tn][1]));
            }
    }

    // epilogue: direct global stores (float2 per fragment half)
#pragma unroll
    for (int tm = 0; tm < 4; tm++) {
        const size_t row0 = (size_t)tokbase + m0 + tm * 16 + r;
        float* ob = out + ((size_t)h * ntok + row0) * D_OUTD + dbase + n0;
#pragma unroll
        for (int tn = 0; tn < 4; tn++) {
            float* o = ob + tn * 8 + 2 * c;
            float2 v0; v0.x = acc[tm][tn][0]; v0.y = acc[tm][tn][1];
            float2 v1; v1.x = acc[tm][tn][2]; v1.y = acc[tm][tn][3];
            *(float2*)o = v0;
            *(float2*)(o + 8 * D_OUTD) = v1;
        }
    }
}

// ---------------------------------------------------------------------------
extern "C" void kernel_launch(void* const* d_in, const int* in_sizes, int n_in,
                              void* d_out, int out_size)
{
    const float* x   = (const float*)d_in[0];
    const float* dw  = (const float*)d_in[1];
    const float* db  = (const float*)d_in[2];
    const float* ntl = (const float*)d_in[3];
    const float* lo  = (const float*)d_in[4];
    const float* gw  = (const float*)d_in[5];
    const float* gb  = (const float*)d_in[6];
    float* out = (float*)d_out;

    int ntok = in_sizes[0] / D_IN;   // 8192

    int smem1 = (TM1 * XROW + NCOL * XROW + 84 + 84 + 12) * (int)sizeof(float);
    cudaFuncSetAttribute(k1_route, cudaFuncAttributeMaxDynamicSharedMemorySize, smem1);
    cudaFuncSetAttribute(k2_mma,   cudaFuncAttributeMaxDynamicSharedMemorySize, SMEM2);

    k0_transpose<<<dim3(D_OUTD / 32, NCOL / 32, NHEADS), dim3(32, 8)>>>(lo);
    k1_route<<<ntok / TM1, T1, smem1>>>(x, dw, db, ntl, gw, gb, ntok);

    dim3 g2(ntok / 128, D_OUTD / 128, NHEADS);
    k2_mma<<<g2, T2, SMEM2>>>(out, ntok);
}

// round 5
// speedup vs baseline: 2.4723x; 1.0594x over previous
#include <cuda_runtime.h>
#include <cstdint>

#define D_IN   1024
#define D_OUTD 1024
#define NTREES 12
#define NINT   7
#define NCOL   96      // 84 decision cols + 12 gate cols; also 12 trees * 8 leaves
#define NHEADS 3
#define MAX_TOK 8192

// scratch
__device__ float g_coef[MAX_TOK * NCOL];          // [tok][j]  (A operand, K-major)
__device__ float g_lot[NHEADS * D_OUTD * NCOL];   // [h][d][j] (B operand, K-major, tf32-rounded)
__device__ float g_w2[2 * NCOL * D_IN];           // [hi|lo][96][1024] tf32-split weights

__device__ __forceinline__ uint32_t cvt_tf32(float f) {
    uint32_t u;
    asm("cvt.rna.tf32.f32 %0, %1;" : "=r"(u) : "f"(f));
    return u;
}
__device__ __forceinline__ uint32_t smem_u32(const void* p) {
    uint32_t a;
    asm("{ .reg .u64 t; cvta.to.shared.u64 t, %1; cvt.u32.u64 %0, t; }" : "=r"(a) : "l"(p));
    return a;
}
__device__ __forceinline__ void cpasync16(uint32_t dst, const void* src) {
    asm volatile("cp.async.cg.shared.global [%0], [%1], 16;" :: "r"(dst), "l"(src) : "memory");
}

#define MMA_TF32(acc, a0, a1, a2, a3, b0, b1)                                   \
    asm("mma.sync.aligned.m16n8k8.row.col.f32.tf32.tf32.f32 "                   \
        "{%0,%1,%2,%3}, {%4,%5,%6,%7}, {%8,%9}, {%0,%1,%2,%3};"                 \
        : "+f"((acc)[0]), "+f"((acc)[1]), "+f"((acc)[2]), "+f"((acc)[3])        \
        : "r"(a0), "r"(a1), "r"(a2), "r"(a3), "r"(b0), "r"(b1))

// ---------------------------------------------------------------------------
// Kernel W: split routing weights into tf32 hi/lo:  g_w2[0|1][row][k]
//   rows 0..83 = decision_weights, 84..95 = gate_w
// ---------------------------------------------------------------------------
__global__ void kw_split(const float* __restrict__ dw, const float* __restrict__ gw)
{
    const int row = blockIdx.x;
    const float* src = (row < 84) ? (dw + (size_t)row * D_IN)
                                  : (gw + (size_t)(row - 84) * D_IN);
    for (int k = threadIdx.x * 4; k < D_IN; k += blockDim.x * 4) {
        float4 v = *(const float4*)&src[k];
        float4 hi, lo;
        hi.x = __uint_as_float(cvt_tf32(v.x)); lo.x = __uint_as_float(cvt_tf32(v.x - hi.x));
        hi.y = __uint_as_float(cvt_tf32(v.y)); lo.y = __uint_as_float(cvt_tf32(v.y - hi.y));
        hi.z = __uint_as_float(cvt_tf32(v.z)); lo.z = __uint_as_float(cvt_tf32(v.z - hi.z));
        hi.w = __uint_as_float(cvt_tf32(v.w)); lo.w = __uint_as_float(cvt_tf32(v.w - hi.w));
        *(float4*)&g_w2[(size_t)row * D_IN + k] = hi;
        *(float4*)&g_w2[(size_t)(NCOL + row) * D_IN + k] = lo;
    }
}

// ---------------------------------------------------------------------------
// Kernel 0: LO transpose [h][j][d] -> [h][d][j] with tf32 rounding
// ---------------------------------------------------------------------------
__global__ void k0_transpose(const float* __restrict__ lo)
{
    __shared__ float t[32][33];
    const int h = blockIdx.z, j0 = blockIdx.y * 32, d0 = blockIdx.x * 32;
    const int tx = threadIdx.x, ty = threadIdx.y;   // 32 x 8
#pragma unroll
    for (int i = 0; i < 32; i += 8)
        t[ty + i][tx] = lo[((size_t)h * NCOL + (j0 + ty + i)) * D_OUTD + d0 + tx];
    __syncthreads();
#pragma unroll
    for (int i = 0; i < 32; i += 8) {
        uint32_t u = cvt_tf32(t[tx][ty + i]);
        g_lot[((size_t)h * D_OUTD + (d0 + ty + i)) * NCOL + j0 + tx] = __uint_as_float(u);
    }
}

// ---------------------------------------------------------------------------
// Kernel 1: routing GEMM on tensor cores (split tf32, 3 MMA terms)
//   Per CTA: 64 tok x 96 col x 1024 K, KC=32 chunks, 2-stage cp.async pipe
//   then sigmoid / leaf products / softmax epilogue -> g_coef
// smem (floats): stage s at s*9216: A 64x36 raw, Bh 96x36, Bl 96x36
//   consts at 18432: sInvT 84, sBias 84, sGb 12;  Ds overlay at 0: 64x100
// ---------------------------------------------------------------------------
#define T1   256
#define KC1  32
#define STAGEF 9216
#define SMEM1 ((2 * STAGEF + 180) * 4)

__global__ __launch_bounds__(T1) void k1_mma(
    const float* __restrict__ x,
    const float* __restrict__ db,
    const float* __restrict__ ntl,
    const float* __restrict__ gb,
    int ntok)
{
    extern __shared__ float sm[];
    const uint32_t sbase = smem_u32(sm);
    float* sInvT = sm + 2 * STAGEF;
    float* sBias = sInvT + 84;
    float* sGb   = sBias + 84;

    const int tid = threadIdx.x;
    const int lane = tid & 31, wid = tid >> 5;
    const int r = lane >> 2, c = lane & 3;
    const int m0 = (wid >> 2) * 32;     // 2 m-warps x 32 rows
    const int n0 = (wid & 3) * 24;      // 4 n-warps x 24 cols
    const int tokbase = blockIdx.x * 64;

    if (tid < 84) {
        float z = ntl[tid] + 0.5413f;
        float sp = (z > 15.f) ? z : log1pf(__expf(z));
        sInvT[tid] = 1.0f / sp;
        sBias[tid] = db[tid];
    } else if (tid >= 96 && tid < 96 + NTREES) {
        sGb[tid - 96] = gb[tid - 96];
    }

    float acc[2][3][4];
#pragma unroll
    for (int tm = 0; tm < 2; tm++)
#pragma unroll
        for (int tn = 0; tn < 3; tn++)
#pragma unroll
            for (int q = 0; q < 4; q++) acc[tm][tn][q] = 0.f;

    // ---- prefetch chunk 0 into stage 0 ----
    {
        const int kb = 0;
#pragma unroll
        for (int i = 0; i < 2; i++) {
            int idx = i * T1 + tid;
            int row = idx >> 3, c4 = idx & 7;
            cpasync16(sbase + (0 * STAGEF + row * 36 + 4 * c4) * 4,
                      &x[(size_t)(tokbase + row) * D_IN + kb + 4 * c4]);
        }
#pragma unroll
        for (int i = 0; i < 3; i++) {
            int idx = i * T1 + tid;
            int row = idx >> 3, c4 = idx & 7;
            const float* sh = &g_w2[(size_t)row * D_IN + kb + 4 * c4];
            cpasync16(sbase + (0 * STAGEF + 2304 + row * 36 + 4 * c4) * 4, sh);
            cpasync16(sbase + (0 * STAGEF + 5760 + row * 36 + 4 * c4) * 4, sh + NCOL * D_IN);
        }
        asm volatile("cp.async.commit_group;" ::: "memory");
    }

    for (int ck = 0; ck < D_IN / KC1; ck++) {
        __syncthreads();   // all warps done computing chunk ck-1 (buffer reuse safety)
        if (ck < D_IN / KC1 - 1) {
            const int s = (ck + 1) & 1;
            const int kb = (ck + 1) * KC1;
#pragma unroll
            for (int i = 0; i < 2; i++) {
                int idx = i * T1 + tid;
                int row = idx >> 3, c4 = idx & 7;
                cpasync16(sbase + (s * STAGEF + row * 36 + 4 * c4) * 4,
                          &x[(size_t)(tokbase + row) * D_IN + kb + 4 * c4]);
            }
#pragma unroll
            for (int i = 0; i < 3; i++) {
                int idx = i * T1 + tid;
                int row = idx >> 3, c4 = idx & 7;
                const float* sh = &g_w2[(size_t)row * D_IN + kb + 4 * c4];
                cpasync16(sbase + (s * STAGEF + 2304 + row * 36 + 4 * c4) * 4, sh);
                cpasync16(sbase + (s * STAGEF + 5760 + row * 36 + 4 * c4) * 4, sh + NCOL * D_IN);
            }
            asm volatile("cp.async.commit_group;" ::: "memory");
            asm volatile("cp.async.wait_group 1;" ::: "memory");
        } else {
            asm volatile("cp.async.wait_group 0;" ::: "memory");
        }
        __syncthreads();

        const float* As = sm + (ck & 1) * STAGEF;
        const float* Bh = As + 2304;
        const float* Bl = As + 5760;

#pragma unroll
        for (int ks = 0; ks < KC1 / 8; ks++) {
            const int k0 = ks * 8;
            uint32_t ah[2][4], al[2][4], bh[3][2], bl[3][2];
#pragma unroll
            for (int tm = 0; tm < 2; tm++) {
                const float* ap = &As[(m0 + tm * 16 + r) * 36 + k0 + c];
                float v0 = ap[0], v1 = ap[8 * 36], v2 = ap[4], v3 = ap[8 * 36 + 4];
                ah[tm][0] = cvt_tf32(v0); al[tm][0] = cvt_tf32(v0 - __uint_as_float(ah[tm][0]));
                ah[tm][1] = cvt_tf32(v1); al[tm][1] = cvt_tf32(v1 - __uint_as_float(ah[tm][1]));
                ah[tm][2] = cvt_tf32(v2); al[tm][2] = cvt_tf32(v2 - __uint_as_float(ah[tm][2]));
                ah[tm][3] = cvt_tf32(v3); al[tm][3] = cvt_tf32(v3 - __uint_as_float(ah[tm][3]));
            }
#pragma unroll
            for (int tn = 0; tn < 3; tn++) {
                const uint32_t* bph = (const uint32_t*)&Bh[(n0 + tn * 8 + r) * 36 + k0 + c];
                const uint32_t* bpl = (const uint32_t*)&Bl[(n0 + tn * 8 + r) * 36 + k0 + c];
                bh[tn][0] = bph[0]; bh[tn][1] = bph[4];
                bl[tn][0] = bpl[0]; bl[tn][1] = bpl[4];
            }
#pragma unroll
            for (int tm = 0; tm < 2; tm++)
#pragma unroll
                for (int tn = 0; tn < 3; tn++) {
                    MMA_TF32(acc[tm][tn], ah[tm][0], ah[tm][1], ah[tm][2], ah[tm][3],
                             bh[tn][0], bh[tn][1]);
                    MMA_TF32(acc[tm][tn], al[tm][0], al[tm][1], al[tm][2], al[tm][3],
                             bh[tn][0], bh[tn][1]);
                    MMA_TF32(acc[tm][tn], ah[tm][0], ah[tm][1], ah[tm][2], ah[tm][3],
                             bl[tn][0], bl[tn][1]);
                }
        }
    }

    // ---- write logits to smem Ds[64][100] ----
    __syncthreads();
    float* Ds = sm;
#pragma unroll
    for (int tm = 0; tm < 2; tm++)
#pragma unroll
        for (int tn = 0; tn < 3; tn++) {
            float* p = &Ds[(m0 + tm * 16 + r) * 100 + n0 + tn * 8 + 2 * c];
            p[0] = acc[tm][tn][0];
            p[1] = acc[tm][tn][1];
            p[8 * 100] = acc[tm][tn][2];
            p[8 * 100 + 1] = acc[tm][tn][3];
        }
    __syncthreads();

    if (tid < 64) {
        const float* d = &Ds[tid * 100];
        float g[NTREES];
        float m = -1e30f;
#pragma unroll
        for (int t = 0; t < NTREES; t++) { g[t] = d[84 + t] + sGb[t]; m = fmaxf(m, g[t]); }
        float s = 0.f;
#pragma unroll
        for (int t = 0; t < NTREES; t++) { g[t] = __expf(g[t] - m); s += g[t]; }
        float inv = 1.0f / s;

        const int tok = tokbase + tid;
        float* orow = &g_coef[(size_t)tok * NCOL];
#pragma unroll
        for (int t = 0; t < NTREES; t++) {
            float w = g[t] * inv;
            float p[NINT];
#pragma unroll
            for (int n = 0; n < NINT; n++) {
                float z = (d[t * 7 + n] + sBias[t * 7 + n]) * sInvT[t * 7 + n];
                p[n] = 1.0f / (1.0f + __expf(-z));
            }
            float a0 = p[0], a1 = 1.f - p[0];
            float4 v0, v1;
            v0.x = w * a0 * p[1] * p[3];
            v0.y = w * a0 * p[1] * (1.f - p[3]);
            v0.z = w * a0 * (1.f - p[1]) * p[4];
            v0.w = w * a0 * (1.f - p[1]) * (1.f - p[4]);
            v1.x = w * a1 * p[2] * p[5];
            v1.y = w * a1 * p[2] * (1.f - p[5]);
            v1.z = w * a1 * (1.f - p[2]) * p[6];
            v1.w = w * a1 * (1.f - p[2]) * (1.f - p[6]);
            *(float4*)&orow[t * 8 + 0] = v0;
            *(float4*)&orow[t * 8 + 4] = v1;
        }
    }
}

// ---------------------------------------------------------------------------
// Kernel 2: mma.sync tf32 GEMM. Per CTA: D[128 tok x 128 d] = A[128x96] B^T
// ---------------------------------------------------------------------------
#define T2 256
#define SROW 100
#define SMEM2 (2 * 128 * SROW * 4)

__global__ __launch_bounds__(T2, 2) void k2_mma(float* __restrict__ out, int ntok)
{
    extern __shared__ float sm2[];
    float* As = sm2;                 // 128 x SROW
    float* Bs = sm2 + 128 * SROW;    // 128 x SROW

    const int tid = threadIdx.x;
    const int tokbase = blockIdx.x * 128;
    const int dbase   = blockIdx.y * 128;
    const int h       = blockIdx.z;

    // stage A with tf32 rounding
#pragma unroll
    for (int i = 0; i < 12; i++) {
        int idx = i * T2 + tid;
        int row = idx / 24, c4 = idx % 24;
        float4 v = *(const float4*)&g_coef[(size_t)(tokbase + row) * NCOL + 4 * c4];
        float4 w;
        w.x = __uint_as_float(cvt_tf32(v.x));
        w.y = __uint_as_float(cvt_tf32(v.y));
        w.z = __uint_as_float(cvt_tf32(v.z));
        w.w = __uint_as_float(cvt_tf32(v.w));
        *(float4*)&As[row * SROW + 4 * c4] = w;
    }
    // stage B (already tf32-rounded)
    const float* bsrc = g_lot + ((size_t)h * D_OUTD + dbase) * NCOL;
#pragma unroll
    for (int i = 0; i < 12; i++) {
        int idx = i * T2 + tid;
        int row = idx / 24, c4 = idx % 24;
        *(float4*)&Bs[row * SROW + 4 * c4] =
            *(const float4*)&bsrc[(size_t)row * NCOL + 4 * c4];
    }
    __syncthreads();

    const int lane = tid & 31, wid = tid >> 5;
    const int m0 = (wid >> 2) * 64;
    const int n0 = (wid & 3) * 32;
    const int r = lane >> 2, c = lane & 3;

    float acc[4][4][4];
#pragma unroll
    for (int tm = 0; tm < 4; tm++)
#pragma unroll
        for (int tn = 0; tn < 4; tn++)
#pragma unroll
            for (int q = 0; q < 4; q++) acc[tm][tn][q] = 0.f;

#pragma unroll
    for (int ks = 0; ks < 12; ks++) {
        const int k0 = ks * 8;
        uint32_t a[4][4], b[4][2];
#pragma unroll
        for (int tm = 0; tm < 4; tm++) {
            const uint32_t* ap = (const uint32_t*)&As[(m0 + tm * 16 + r) * SROW + k0 + c];
            a[tm][0] = ap[0];
            a[tm][1] = ap[8 * SROW];
            a[tm][2] = ap[4];
            a[tm][3] = ap[8 * SROW + 4];
        }
#pragma unroll
        for (int tn = 0; tn < 4; tn++) {
            const uint32_t* bp = (const uint32_t*)&Bs[(n0 + tn * 8 + r) * SROW + k0 + c];
            b[tn][0] = bp[0];
            b[tn][1] = bp[4];
        }
#pragma unroll
        for (int tm = 0; tm < 4; tm++)
#pragma unroll
            for (int tn = 0; tn < 4; tn++) {
                MMA_TF32(acc[tm][tn], a[tm][0], a[tm][1], a[tm][2], a[tm][3],
                         b[tn][0], b[tn][1]);
            }
    }

#pragma unroll
    for (int tm = 0; tm < 4; tm++) {
        const size_t row0 = (size_t)tokbase + m0 + tm * 16 + r;
        float* ob = out + ((size_t)h * ntok + row0) * D_OUTD + dbase + n0;
#pragma unroll
        for (int tn = 0; tn < 4; tn++) {
            float* o = ob + tn * 8 + 2 * c;
            float2 v0; v0.x = acc[tm][tn][0]; v0.y = acc[tm][tn][1];
            float2 v1; v1.x = acc[tm][tn][2]; v1.y = acc[tm][tn][3];
            *(float2*)o = v0;
            *(float2*)(o + 8 * D_OUTD) = v1;
        }
    }
}

// ---------------------------------------------------------------------------
extern "C" void kernel_launch(void* const* d_in, const int* in_sizes, int n_in,
                              void* d_out, int out_size)
{
    const float* x   = (const float*)d_in[0];
    const float* dw  = (const float*)d_in[1];
    const float* db  = (const float*)d_in[2];
    const float* ntl = (const float*)d_in[3];
    const float* lo  = (const float*)d_in[4];
    const float* gw  = (const float*)d_in[5];
    const float* gb  = (const float*)d_in[6];
    float* out = (float*)d_out;

    int ntok = in_sizes[0] / D_IN;   // 8192

    cudaFuncSetAttribute(k1_mma, cudaFuncAttributeMaxDynamicSharedMemorySize, SMEM1);
    cudaFuncSetAttribute(k2_mma, cudaFuncAttributeMaxDynamicSharedMemorySize, SMEM2);

    kw_split<<<NCOL, 256>>>(dw, gw);
    k0_transpose<<<dim3(D_OUTD / 32, NCOL / 32, NHEADS), dim3(32, 8)>>>(lo);
    k1_mma<<<ntok / 64, T1, SMEM1>>>(x, db, ntl, gb, ntok);

    dim3 g2(ntok / 128, D_OUTD / 128, NHEADS);
    k2_mma<<<g2, T2, SMEM2>>>(out, ntok);
}

// round 6
// speedup vs baseline: 3.1564x; 1.2767x over previous
#include <cuda_runtime.h>
#include <cstdint>

#define D_IN   1024
#define D_OUTD 1024
#define NTREES 12
#define NINT   7
#define NCOL   96      // 84 decision cols + 12 gate cols; also 12 trees * 8 leaves
#define NHEADS 3
#define MAX_TOK 8192

// scratch
__device__ float    g_coef[MAX_TOK * NCOL];        // [tok][j]  (k2 A operand, K-major)
__device__ float    g_lot[NHEADS * D_OUTD * NCOL]; // [h][d][j] (k2 B operand, tf32-rounded)
__device__ uint32_t g_wbfu[2 * NCOL * (D_IN / 2)]; // bf16x2 planes: [hi|lo][96][1024]

__device__ __forceinline__ uint32_t cvt_tf32(float f) {
    uint32_t u;
    asm("cvt.rna.tf32.f32 %0, %1;" : "=r"(u) : "f"(f));
    return u;
}
__device__ __forceinline__ uint32_t smem_u32(const void* p) {
    uint32_t a;
    asm("{ .reg .u64 t; cvta.to.shared.u64 t, %1; cvt.u32.u64 %0, t; }" : "=r"(a) : "l"(p));
    return a;
}
__device__ __forceinline__ void cpasync16(uint32_t dst, const void* src) {
    asm volatile("cp.async.cg.shared.global [%0], [%1], 16;" :: "r"(dst), "l"(src) : "memory");
}
// split float2 (v.x = even k, v.y = odd k) into bf16x2 hi + bf16x2 residual lo
__device__ __forceinline__ void bsplit(float2 v, uint32_t& hi, uint32_t& lo) {
    asm("cvt.rn.bf16x2.f32 %0, %1, %2;" : "=r"(hi) : "f"(v.y), "f"(v.x));
    float fx = __uint_as_float(hi << 16);
    float fy = __uint_as_float(hi & 0xFFFF0000u);
    asm("cvt.rn.bf16x2.f32 %0, %1, %2;" : "=r"(lo) : "f"(v.y - fy), "f"(v.x - fx));
}

#define MMA_TF32(acc, a0, a1, a2, a3, b0, b1)                                   \
    asm("mma.sync.aligned.m16n8k8.row.col.f32.tf32.tf32.f32 "                   \
        "{%0,%1,%2,%3}, {%4,%5,%6,%7}, {%8,%9}, {%0,%1,%2,%3};"                 \
        : "+f"((acc)[0]), "+f"((acc)[1]), "+f"((acc)[2]), "+f"((acc)[3])        \
        : "r"(a0), "r"(a1), "r"(a2), "r"(a3), "r"(b0), "r"(b1))

#define MMA_BF16(acc, a, b)                                                     \
    asm("mma.sync.aligned.m16n8k16.row.col.f32.bf16.bf16.f32 "                  \
        "{%0,%1,%2,%3}, {%4,%5,%6,%7}, {%8,%9}, {%0,%1,%2,%3};"                 \
        : "+f"((acc)[0]), "+f"((acc)[1]), "+f"((acc)[2]), "+f"((acc)[3])        \
        : "r"((a)[0]), "r"((a)[1]), "r"((a)[2]), "r"((a)[3]),                   \
          "r"((b)[0]), "r"((b)[1]))

// ---------------------------------------------------------------------------
// Kernel W: split routing weights into bf16 hi/lo planes
// ---------------------------------------------------------------------------
__global__ void kw_split(const float* __restrict__ dw, const float* __restrict__ gw)
{
    const int row = blockIdx.x;
    const float* src = (row < 84) ? (dw + (size_t)row * D_IN)
                                  : (gw + (size_t)(row - 84) * D_IN);
    for (int k = threadIdx.x * 4; k < D_IN; k += blockDim.x * 4) {
        float4 v = *(const float4*)&src[k];
        uint32_t h0, l0, h1, l1;
        float2 p0; p0.x = v.x; p0.y = v.y;
        float2 p1; p1.x = v.z; p1.y = v.w;
        bsplit(p0, h0, l0);
        bsplit(p1, h1, l1);
        uint32_t o = (uint32_t)(row * D_IN + k) >> 1;
        g_wbfu[o] = h0;  g_wbfu[o + 1] = h1;
        g_wbfu[NCOL * (D_IN / 2) + o] = l0;  g_wbfu[NCOL * (D_IN / 2) + o + 1] = l1;
    }
}

// ---------------------------------------------------------------------------
// Kernel 0: LO transpose [h][j][d] -> [h][d][j] with tf32 rounding
// ---------------------------------------------------------------------------
__global__ void k0_transpose(const float* __restrict__ lo)
{
    __shared__ float t[32][33];
    const int h = blockIdx.z, j0 = blockIdx.y * 32, d0 = blockIdx.x * 32;
    const int tx = threadIdx.x, ty = threadIdx.y;   // 32 x 8
#pragma unroll
    for (int i = 0; i < 32; i += 8)
        t[ty + i][tx] = lo[((size_t)h * NCOL + (j0 + ty + i)) * D_OUTD + d0 + tx];
    __syncthreads();
#pragma unroll
    for (int i = 0; i < 32; i += 8) {
        uint32_t u = cvt_tf32(t[tx][ty + i]);
        g_lot[((size_t)h * D_OUTD + (d0 + ty + i)) * NCOL + j0 + tx] = __uint_as_float(u);
    }
}

// ---------------------------------------------------------------------------
// Kernel 1: routing GEMM, bf16x3 split on tensor cores
//   Per CTA: 64 tok x 96 col x 1024 K, KC=64 chunks, 2-stage cp.async pipe.
// smem stage (floats): Xs 64x72 f32 (4608), Bh 96x36 u32 (3456), Bl (3456)
// ---------------------------------------------------------------------------
#define T1    256
#define KC1   64
#define STG1F 11520
#define SMEM1 ((2 * STG1F + 192) * 4)

__device__ __forceinline__ void k1_stage(uint32_t base, const float* x, int tokbase,
                                          int kb, int tid)
{
#pragma unroll
    for (int i = 0; i < 4; i++) {                 // x: 64 rows x 16 float4
        int idx = i * T1 + tid;
        int row = idx >> 4, c4 = idx & 15;
        cpasync16(base + (uint32_t)(row * 72 + 4 * c4) * 4,
                  &x[(size_t)(tokbase + row) * D_IN + kb + 4 * c4]);
    }
#pragma unroll
    for (int i = 0; i < 6; i++) {                 // w: 2 halves x 96 rows x 8 cp16
        int idx = i * T1 + tid;
        int half = idx / 768, rem = idx % 768;
        int row = rem >> 3, q = rem & 7;
        const char* src = (const char*)g_wbfu + (size_t)half * (NCOL * D_IN * 2)
                        + (size_t)row * (D_IN * 2) + kb * 2 + q * 16;
        cpasync16(base + (uint32_t)(4608 + half * 3456 + row * 36 + 4 * q) * 4, src);
    }
}

__global__ __launch_bounds__(T1) void k1_mma(
    const float* __restrict__ x,
    const float* __restrict__ db,
    const float* __restrict__ ntl,
    const float* __restrict__ gb,
    int ntok)
{
    extern __shared__ float sm[];
    const uint32_t sbase = smem_u32(sm);
    float* sInvT = sm + 2 * STG1F;
    float* sBias = sInvT + 84;
    float* sGb   = sBias + 84;

    const int tid = threadIdx.x;
    const int lane = tid & 31, wid = tid >> 5;
    const int r = lane >> 2, c = lane & 3;
    const int m0 = (wid >> 2) * 32;     // 2 m-warps x 32 rows
    const int n0 = (wid & 3) * 24;      // 4 n-warps x 24 cols
    const int tokbase = blockIdx.x * 64;

    if (tid < 84) {
        float z = ntl[tid] + 0.5413f;
        float sp = (z > 15.f) ? z : log1pf(__expf(z));
        sInvT[tid] = 1.0f / sp;
        sBias[tid] = db[tid];
    } else if (tid >= 96 && tid < 96 + NTREES) {
        sGb[tid - 96] = gb[tid - 96];
    }

    float acc[2][3][4];
#pragma unroll
    for (int tm = 0; tm < 2; tm++)
#pragma unroll
        for (int tn = 0; tn < 3; tn++)
#pragma unroll
            for (int q = 0; q < 4; q++) acc[tm][tn][q] = 0.f;

    k1_stage(sbase, x, tokbase, 0, tid);
    asm volatile("cp.async.commit_group;" ::: "memory");

    for (int ck = 0; ck < D_IN / KC1; ck++) {
        __syncthreads();
        if (ck < D_IN / KC1 - 1) {
            k1_stage(sbase + ((ck + 1) & 1) * STG1F * 4, x, tokbase, (ck + 1) * KC1, tid);
            asm volatile("cp.async.commit_group;" ::: "memory");
            asm volatile("cp.async.wait_group 1;" ::: "memory");
        } else {
            asm volatile("cp.async.wait_group 0;" ::: "memory");
        }
        __syncthreads();

        const float* Xs = sm + (ck & 1) * STG1F;
        const uint32_t* BhU = (const uint32_t*)(Xs + 4608);
        const uint32_t* BlU = (const uint32_t*)(Xs + 8064);

#pragma unroll
        for (int ks = 0; ks < KC1 / 16; ks++) {
            const int kk = ks * 16;
            uint32_t ah[2][4], al[2][4];
#pragma unroll
            for (int tm = 0; tm < 2; tm++) {
                const float* p0 = &Xs[(m0 + tm * 16 + r) * 72 + kk + 2 * c];
                float2 v0 = *(const float2*)p0;
                float2 v1 = *(const float2*)(p0 + 8 * 72);
                float2 v2 = *(const float2*)(p0 + 8);
                float2 v3 = *(const float2*)(p0 + 8 * 72 + 8);
                bsplit(v0, ah[tm][0], al[tm][0]);
                bsplit(v1, ah[tm][1], al[tm][1]);
                bsplit(v2, ah[tm][2], al[tm][2]);
                bsplit(v3, ah[tm][3], al[tm][3]);
            }
            uint32_t bh[3][2], bl[3][2];
#pragma unroll
            for (int tn = 0; tn < 3; tn++) {
                int ro = (n0 + tn * 8 + r) * 36 + ks * 8 + c;
                bh[tn][0] = BhU[ro]; bh[tn][1] = BhU[ro + 4];
                bl[tn][0] = BlU[ro]; bl[tn][1] = BlU[ro + 4];
            }
#pragma unroll
            for (int tm = 0; tm < 2; tm++)
#pragma unroll
                for (int tn = 0; tn < 3; tn++) {
                    MMA_BF16(acc[tm][tn], ah[tm], bh[tn]);
                    MMA_BF16(acc[tm][tn], al[tm], bh[tn]);
                    MMA_BF16(acc[tm][tn], ah[tm], bl[tn]);
                }
        }
    }

    // ---- logits to smem Ds[64][100], then scalar epilogue ----
    __syncthreads();
    float* Ds = sm;
#pragma unroll
    for (int tm = 0; tm < 2; tm++)
#pragma unroll
        for (int tn = 0; tn < 3; tn++) {
            float* p = &Ds[(m0 + tm * 16 + r) * 100 + n0 + tn * 8 + 2 * c];
            p[0] = acc[tm][tn][0];
            p[1] = acc[tm][tn][1];
            p[8 * 100] = acc[tm][tn][2];
            p[8 * 100 + 1] = acc[tm][tn][3];
        }
    __syncthreads();

    if (tid < 64) {
        const float* d = &Ds[tid * 100];
        float g[NTREES];
        float m = -1e30f;
#pragma unroll
        for (int t = 0; t < NTREES; t++) { g[t] = d[84 + t] + sGb[t]; m = fmaxf(m, g[t]); }
        float s = 0.f;
#pragma unroll
        for (int t = 0; t < NTREES; t++) { g[t] = __expf(g[t] - m); s += g[t]; }
        float inv = 1.0f / s;

        const int tok = tokbase + tid;
        float* orow = &g_coef[(size_t)tok * NCOL];
#pragma unroll
        for (int t = 0; t < NTREES; t++) {
            float w = g[t] * inv;
            float p[NINT];
#pragma unroll
            for (int n = 0; n < NINT; n++) {
                float z = (d[t * 7 + n] + sBias[t * 7 + n]) * sInvT[t * 7 + n];
                p[n] = 1.0f / (1.0f + __expf(-z));
            }
            float a0 = p[0], a1 = 1.f - p[0];
            float4 v0, v1;
            v0.x = w * a0 * p[1] * p[3];
            v0.y = w * a0 * p[1] * (1.f - p[3]);
            v0.z = w * a0 * (1.f - p[1]) * p[4];
            v0.w = w * a0 * (1.f - p[1]) * (1.f - p[4]);
            v1.x = w * a1 * p[2] * p[5];
            v1.y = w * a1 * p[2] * (1.f - p[5]);
            v1.z = w * a1 * (1.f - p[2]) * p[6];
            v1.w = w * a1 * (1.f - p[2]) * (1.f - p[6]);
            *(float4*)&orow[t * 8 + 0] = v0;
            *(float4*)&orow[t * 8 + 4] = v1;
        }
    }
}

// ---------------------------------------------------------------------------
// Kernel 2: persistent-B tf32 MMA.
//   CTA = (d-tile 256, head); loops m-tiles (128 tok) with stride 12.
//   B staged once (256x100), A double-buffered via cp.async (2 x 128x100).
//   8 warps 2m x 4n, warp tile 64x64.
// ---------------------------------------------------------------------------
#define T2    256
#define SR2   100
#define BS2F  (256 * SR2)             // 25600
#define AS2F  (128 * SR2)             // 12800
#define SMEM2 ((BS2F + 2 * AS2F) * 4) // 204800

__device__ __forceinline__ void k2_stageA(uint32_t base, int tokbase, int tid)
{
#pragma unroll
    for (int i = 0; i < 12; i++) {
        int idx = i * T2 + tid;
        int row = idx / 24, c4 = idx % 24;
        cpasync16(base + (uint32_t)(row * SR2 + 4 * c4) * 4,
                  &g_coef[(size_t)(tokbase + row) * NCOL + 4 * c4]);
    }
}

__global__ __launch_bounds__(T2, 1) void k2_mma(float* __restrict__ out, int ntok)
{
    extern __shared__ float sm2[];
    const uint32_t sbase = smem_u32(sm2);
    float* Bs = sm2;

    const int tid = threadIdx.x;
    const int lane = tid & 31, wid = tid >> 5;
    const int r = lane >> 2, c = lane & 3;
    const int m0 = (wid >> 2) * 64;    // 2 m-warps x 64
    const int n0 = (wid & 3) * 64;     // 4 n-warps x 64
    const int dbase = blockIdx.x * 256;
    const int h     = blockIdx.y;
    const int s     = blockIdx.z;      // 0..11

    // stage B once + first A
#pragma unroll
    for (int i = 0; i < 24; i++) {
        int idx = i * T2 + tid;
        int row = idx / 24, c4 = idx % 24;
        cpasync16(sbase + (uint32_t)(row * SR2 + 4 * c4) * 4,
                  &g_lot[((size_t)h * D_OUTD + dbase + row) * NCOL + 4 * c4]);
    }
    k2_stageA(sbase + BS2F * 4, s * 128, tid);
    asm volatile("cp.async.commit_group;" ::: "memory");

    int it = 0;
    for (int mt = s; mt < 64; mt += 12, it++) {
        const int buf = it & 1;
        __syncthreads();   // everyone done reading buf^1 from previous iter
        if (mt + 12 < 64) {
            k2_stageA(sbase + (BS2F + (buf ^ 1) * AS2F) * 4, (mt + 12) * 128, tid);
            asm volatile("cp.async.commit_group;" ::: "memory");
            asm volatile("cp.async.wait_group 1;" ::: "memory");
        } else {
            asm volatile("cp.async.wait_group 0;" ::: "memory");
        }
        __syncthreads();

        const float* As = sm2 + BS2F + buf * AS2F;

        float acc[4][8][4];
#pragma unroll
        for (int tm = 0; tm < 4; tm++)
#pragma unroll
            for (int tn = 0; tn < 8; tn++)
#pragma unroll
                for (int q = 0; q < 4; q++) acc[tm][tn][q] = 0.f;

#pragma unroll
        for (int ks = 0; ks < 12; ks++) {
            const int k0 = ks * 8;
            uint32_t a[4][4], b[8][2];
#pragma unroll
            for (int tm = 0; tm < 4; tm++) {
                const float* ap = &As[(m0 + tm * 16 + r) * SR2 + k0 + c];
                a[tm][0] = cvt_tf32(ap[0]);
                a[tm][1] = cvt_tf32(ap[8 * SR2]);
                a[tm][2] = cvt_tf32(ap[4]);
                a[tm][3] = cvt_tf32(ap[8 * SR2 + 4]);
            }
#pragma unroll
            for (int tn = 0; tn < 8; tn++) {
                const uint32_t* bp = (const uint32_t*)&Bs[(n0 + tn * 8 + r) * SR2 + k0 + c];
                b[tn][0] = bp[0];
                b[tn][1] = bp[4];
            }
#pragma unroll
            for (int tm = 0; tm < 4; tm++)
#pragma unroll
                for (int tn = 0; tn < 8; tn++)
                    MMA_TF32(acc[tm][tn], a[tm][0], a[tm][1], a[tm][2], a[tm][3],
                             b[tn][0], b[tn][1]);
        }

        // epilogue for this m-tile
        const int tokbase = mt * 128;
#pragma unroll
        for (int tm = 0; tm < 4; tm++) {
            const size_t row0 = (size_t)tokbase + m0 + tm * 16 + r;
            float* ob = out + ((size_t)h * ntok + row0) * D_OUTD + dbase + n0;
#pragma unroll
            for (int tn = 0; tn < 8; tn++) {
                float* o = ob + tn * 8 + 2 * c;
                float2 v0; v0.x = acc[tm][tn][0]; v0.y = acc[tm][tn][1];
                float2 v1; v1.x = acc[tm][tn][2]; v1.y = acc[tm][tn][3];
                *(float2*)o = v0;
                *(float2*)(o + 8 * D_OUTD) = v1;
            }
        }
    }
}

// ---------------------------------------------------------------------------
extern "C" void kernel_launch(void* const* d_in, const int* in_sizes, int n_in,
                              void* d_out, int out_size)
{
    const float* x   = (const float*)d_in[0];
    const float* dw  = (const float*)d_in[1];
    const float* db  = (const float*)d_in[2];
    const float* ntl = (const float*)d_in[3];
    const float* lo  = (const float*)d_in[4];
    const float* gw  = (const float*)d_in[5];
    const float* gb  = (const float*)d_in[6];
    float* out = (float*)d_out;

    int ntok = in_sizes[0] / D_IN;   // 8192

    cudaFuncSetAttribute(k1_mma, cudaFuncAttributeMaxDynamicSharedMemorySize, SMEM1);
    cudaFuncSetAttribute(k2_mma, cudaFuncAttributeMaxDynamicSharedMemorySize, SMEM2);

    kw_split<<<NCOL, 256>>>(dw, gw);
    k0_transpose<<<dim3(D_OUTD / 32, NCOL / 32, NHEADS), dim3(32, 8)>>>(lo);
    k1_mma<<<ntok / 64, T1, SMEM1>>>(x, db, ntl, gb, ntok);

    dim3 g2(D_OUTD / 256, NHEADS, 12);
    k2_mma<<<g2, T2, SMEM2>>>(out, ntok);
}

// round 7
// speedup vs baseline: 4.0055x; 1.2690x over previous
#include <cuda_runtime.h>
#include <cuda_fp16.h>
#include <cstdint>

#define D_IN   1024
#define D_OUTD 1024
#define NTREES 12
#define NINT   7
#define NCOL   96      // 84 decision cols + 12 gate cols; also 12 trees * 8 leaves
#define NHEADS 3
#define MAX_TOK 8192

// scratch
__device__ __half   g_coefh[MAX_TOK * NCOL];        // [tok][j]  (k2 A operand, fp16)
__device__ __half   g_loth[NHEADS * D_OUTD * NCOL]; // [h][d][j] (k2 B operand, fp16)
__device__ uint32_t g_wbfu[2 * NCOL * (D_IN / 2)];  // bf16x2 planes: [hi|lo][96][1024]

__device__ __forceinline__ uint32_t smem_u32(const void* p) {
    uint32_t a;
    asm("{ .reg .u64 t; cvta.to.shared.u64 t, %1; cvt.u32.u64 %0, t; }" : "=r"(a) : "l"(p));
    return a;
}
__device__ __forceinline__ void cpasync16(uint32_t dst, const void* src) {
    asm volatile("cp.async.cg.shared.global [%0], [%1], 16;" :: "r"(dst), "l"(src) : "memory");
}
// split float2 (v.x = even k, v.y = odd k) into bf16x2 hi + bf16x2 residual lo
__device__ __forceinline__ void bsplit(float2 v, uint32_t& hi, uint32_t& lo) {
    asm("cvt.rn.bf16x2.f32 %0, %1, %2;" : "=r"(hi) : "f"(v.y), "f"(v.x));
    float fx = __uint_as_float(hi << 16);
    float fy = __uint_as_float(hi & 0xFFFF0000u);
    asm("cvt.rn.bf16x2.f32 %0, %1, %2;" : "=r"(lo) : "f"(v.y - fy), "f"(v.x - fx));
}

#define MMA_BF16(acc, a, b)                                                     \
    asm("mma.sync.aligned.m16n8k16.row.col.f32.bf16.bf16.f32 "                  \
        "{%0,%1,%2,%3}, {%4,%5,%6,%7}, {%8,%9}, {%0,%1,%2,%3};"                 \
        : "+f"((acc)[0]), "+f"((acc)[1]), "+f"((acc)[2]), "+f"((acc)[3])        \
        : "r"((a)[0]), "r"((a)[1]), "r"((a)[2]), "r"((a)[3]),                   \
          "r"((b)[0]), "r"((b)[1]))

#define MMA_F16(acc, a, b)                                                      \
    asm("mma.sync.aligned.m16n8k16.row.col.f32.f16.f16.f32 "                    \
        "{%0,%1,%2,%3}, {%4,%5,%6,%7}, {%8,%9}, {%0,%1,%2,%3};"                 \
        : "+f"((acc)[0]), "+f"((acc)[1]), "+f"((acc)[2]), "+f"((acc)[3])        \
        : "r"((a)[0]), "r"((a)[1]), "r"((a)[2]), "r"((a)[3]),                   \
          "r"((b)[0]), "r"((b)[1]))

#define LDMX4(r0, r1, r2, r3, addr)                                             \
    asm volatile("ldmatrix.sync.aligned.m8n8.x4.shared.b16 {%0,%1,%2,%3}, [%4];"\
        : "=r"(r0), "=r"(r1), "=r"(r2), "=r"(r3) : "r"(addr))

// ---------------------------------------------------------------------------
// Kernel W: split routing weights into bf16 hi/lo planes
// ---------------------------------------------------------------------------
__global__ void kw_split(const float* __restrict__ dw, const float* __restrict__ gw)
{
    const int row = blockIdx.x;
    const float* src = (row < 84) ? (dw + (size_t)row * D_IN)
                                  : (gw + (size_t)(row - 84) * D_IN);
    for (int k = threadIdx.x * 4; k < D_IN; k += blockDim.x * 4) {
        float4 v = *(const float4*)&src[k];
        uint32_t h0, l0, h1, l1;
        float2 p0; p0.x = v.x; p0.y = v.y;
        float2 p1; p1.x = v.z; p1.y = v.w;
        bsplit(p0, h0, l0);
        bsplit(p1, h1, l1);
        uint32_t o = (uint32_t)(row * D_IN + k) >> 1;
        g_wbfu[o] = h0;  g_wbfu[o + 1] = h1;
        g_wbfu[NCOL * (D_IN / 2) + o] = l0;  g_wbfu[NCOL * (D_IN / 2) + o + 1] = l1;
    }
}

// ---------------------------------------------------------------------------
// Kernel 0: LO transpose [h][j][d] -> [h][d][j], fp16 output
// ---------------------------------------------------------------------------
__global__ void k0_transpose(const float* __restrict__ lo)
{
    __shared__ float t[32][33];
    const int h = blockIdx.z, j0 = blockIdx.y * 32, d0 = blockIdx.x * 32;
    const int tx = threadIdx.x, ty = threadIdx.y;   // 32 x 8
#pragma unroll
    for (int i = 0; i < 32; i += 8)
        t[ty + i][tx] = lo[((size_t)h * NCOL + (j0 + ty + i)) * D_OUTD + d0 + tx];
    __syncthreads();
#pragma unroll
    for (int i = 0; i < 32; i += 8)
        g_loth[((size_t)h * D_OUTD + (d0 + ty + i)) * NCOL + j0 + tx] =
            __float2half_rn(t[tx][ty + i]);
}

// ---------------------------------------------------------------------------
// Kernel 1: routing GEMM, bf16x3 split on tensor cores (unchanged mainloop)
// ---------------------------------------------------------------------------
#define T1    256
#define KC1   64
#define STG1F 11520
#define SMEM1 ((2 * STG1F + 192) * 4)

__device__ __forceinline__ void k1_stage(uint32_t base, const float* x, int tokbase,
                                          int kb, int tid)
{
#pragma unroll
    for (int i = 0; i < 4; i++) {                 // x: 64 rows x 16 float4
        int idx = i * T1 + tid;
        int row = idx >> 4, c4 = idx & 15;
        cpasync16(base + (uint32_t)(row * 72 + 4 * c4) * 4,
                  &x[(size_t)(tokbase + row) * D_IN + kb + 4 * c4]);
    }
#pragma unroll
    for (int i = 0; i < 6; i++) {                 // w: 2 halves x 96 rows x 8 cp16
        int idx = i * T1 + tid;
        int half_ = idx / 768, rem = idx % 768;
        int row = rem >> 3, q = rem & 7;
        const char* src = (const char*)g_wbfu + (size_t)half_ * (NCOL * D_IN * 2)
                        + (size_t)row * (D_IN * 2) + kb * 2 + q * 16;
        cpasync16(base + (uint32_t)(4608 + half_ * 3456 + row * 36 + 4 * q) * 4, src);
    }
}

__global__ __launch_bounds__(T1) void k1_mma(
    const float* __restrict__ x,
    const float* __restrict__ db,
    const float* __restrict__ ntl,
    const float* __restrict__ gb,
    int ntok)
{
    extern __shared__ float sm[];
    const uint32_t sbase = smem_u32(sm);
    float* sInvT = sm + 2 * STG1F;
    float* sBias = sInvT + 84;
    float* sGb   = sBias + 84;

    const int tid = threadIdx.x;
    const int lane = tid & 31, wid = tid >> 5;
    const int r = lane >> 2, c = lane & 3;
    const int m0 = (wid >> 2) * 32;     // 2 m-warps x 32 rows
    const int n0 = (wid & 3) * 24;      // 4 n-warps x 24 cols
    const int tokbase = blockIdx.x * 64;

    if (tid < 84) {
        float z = ntl[tid] + 0.5413f;
        float sp = (z > 15.f) ? z : log1pf(__expf(z));
        sInvT[tid] = 1.0f / sp;
        sBias[tid] = db[tid];
    } else if (tid >= 96 && tid < 96 + NTREES) {
        sGb[tid - 96] = gb[tid - 96];
    }

    float acc[2][3][4];
#pragma unroll
    for (int tm = 0; tm < 2; tm++)
#pragma unroll
        for (int tn = 0; tn < 3; tn++)
#pragma unroll
            for (int q = 0; q < 4; q++) acc[tm][tn][q] = 0.f;

    k1_stage(sbase, x, tokbase, 0, tid);
    asm volatile("cp.async.commit_group;" ::: "memory");

    for (int ck = 0; ck < D_IN / KC1; ck++) {
        __syncthreads();
        if (ck < D_IN / KC1 - 1) {
            k1_stage(sbase + ((ck + 1) & 1) * STG1F * 4, x, tokbase, (ck + 1) * KC1, tid);
            asm volatile("cp.async.commit_group;" ::: "memory");
            asm volatile("cp.async.wait_group 1;" ::: "memory");
        } else {
            asm volatile("cp.async.wait_group 0;" ::: "memory");
        }
        __syncthreads();

        const float* Xs = sm + (ck & 1) * STG1F;
        const uint32_t* BhU = (const uint32_t*)(Xs + 4608);
        const uint32_t* BlU = (const uint32_t*)(Xs + 8064);

#pragma unroll
        for (int ks = 0; ks < KC1 / 16; ks++) {
            const int kk = ks * 16;
            uint32_t ah[2][4], al[2][4];
#pragma unroll
            for (int tm = 0; tm < 2; tm++) {
                const float* p0 = &Xs[(m0 + tm * 16 + r) * 72 + kk + 2 * c];
                float2 v0 = *(const float2*)p0;
                float2 v1 = *(const float2*)(p0 + 8 * 72);
                float2 v2 = *(const float2*)(p0 + 8);
                float2 v3 = *(const float2*)(p0 + 8 * 72 + 8);
                bsplit(v0, ah[tm][0], al[tm][0]);
                bsplit(v1, ah[tm][1], al[tm][1]);
                bsplit(v2, ah[tm][2], al[tm][2]);
                bsplit(v3, ah[tm][3], al[tm][3]);
            }
            uint32_t bh[3][2], bl[3][2];
#pragma unroll
            for (int tn = 0; tn < 3; tn++) {
                int ro = (n0 + tn * 8 + r) * 36 + ks * 8 + c;
                bh[tn][0] = BhU[ro]; bh[tn][1] = BhU[ro + 4];
                bl[tn][0] = BlU[ro]; bl[tn][1] = BlU[ro + 4];
            }
#pragma unroll
            for (int tm = 0; tm < 2; tm++)
#pragma unroll
                for (int tn = 0; tn < 3; tn++) {
                    MMA_BF16(acc[tm][tn], ah[tm], bh[tn]);
                    MMA_BF16(acc[tm][tn], al[tm], bh[tn]);
                    MMA_BF16(acc[tm][tn], ah[tm], bl[tn]);
                }
        }
    }

    // ---- logits to smem Ds[64][100], then scalar epilogue ----
    __syncthreads();
    float* Ds = sm;
#pragma unroll
    for (int tm = 0; tm < 2; tm++)
#pragma unroll
        for (int tn = 0; tn < 3; tn++) {
            float* p = &Ds[(m0 + tm * 16 + r) * 100 + n0 + tn * 8 + 2 * c];
            p[0] = acc[tm][tn][0];
            p[1] = acc[tm][tn][1];
            p[8 * 100] = acc[tm][tn][2];
            p[8 * 100 + 1] = acc[tm][tn][3];
        }
    __syncthreads();

    if (tid < 64) {
        const float* d = &Ds[tid * 100];
        float g[NTREES];
        float m = -1e30f;
#pragma unroll
        for (int t = 0; t < NTREES; t++) { g[t] = d[84 + t] + sGb[t]; m = fmaxf(m, g[t]); }
        float s = 0.f;
#pragma unroll
        for (int t = 0; t < NTREES; t++) { g[t] = __expf(g[t] - m); s += g[t]; }
        float inv = 1.0f / s;

        const int tok = tokbase + tid;
        __half2* orow = (__half2*)&g_coefh[(size_t)tok * NCOL];
#pragma unroll
        for (int t = 0; t < NTREES; t++) {
            float w = g[t] * inv;
            float p[NINT];
#pragma unroll
            for (int n = 0; n < NINT; n++) {
                float z = (d[t * 7 + n] + sBias[t * 7 + n]) * sInvT[t * 7 + n];
                p[n] = 1.0f / (1.0f + __expf(-z));
            }
            float a0 = p[0], a1 = 1.f - p[0];
            orow[t * 4 + 0] = __floats2half2_rn(w * a0 * p[1] * p[3],
                                                w * a0 * p[1] * (1.f - p[3]));
            orow[t * 4 + 1] = __floats2half2_rn(w * a0 * (1.f - p[1]) * p[4],
                                                w * a0 * (1.f - p[1]) * (1.f - p[4]));
            orow[t * 4 + 2] = __floats2half2_rn(w * a1 * p[2] * p[5],
                                                w * a1 * p[2] * (1.f - p[5]));
            orow[t * 4 + 3] = __floats2half2_rn(w * a1 * (1.f - p[2]) * p[6],
                                                w * a1 * (1.f - p[2]) * (1.f - p[6]));
        }
    }
}

// ---------------------------------------------------------------------------
// Kernel 2: persistent-B fp16 MMA with ldmatrix.
//   Grid (8 d-tiles, 3 heads, 12 s) = 288 CTAs, 2 CTAs/SM.
//   CTA tile 128 tok x 128 d; 8 warps 2m x 4n, warp tile 64x32.
//   B staged once (128 x 96 halfs), A double-buffered (2 x 128 x 96).
// ---------------------------------------------------------------------------
#define T2    256
#define SA2   104                      // halfs per smem row (208B, conflict-free)
#define BS2H  (128 * SA2)
#define AS2H  (128 * SA2)
#define SMEM2 ((BS2H + 2 * AS2H) * 2)  // 79872 B

__device__ __forceinline__ void k2_stageA(uint32_t base, int tokbase, int tid)
{
#pragma unroll
    for (int i = 0; i < 6; i++) {      // 128 rows x 12 cp16
        int idx = i * T2 + tid;
        int row = idx / 12, q = idx % 12;
        cpasync16(base + (uint32_t)(row * SA2 + q * 8) * 2,
                  &g_coefh[(size_t)(tokbase + row) * NCOL + q * 8]);
    }
}

__global__ __launch_bounds__(T2, 2) void k2_mma(float* __restrict__ out, int ntok)
{
    extern __shared__ __half smh[];
    const uint32_t sbase = smem_u32(smh);

    const int tid = threadIdx.x;
    const int lane = tid & 31, wid = tid >> 5;
    const int m0 = (wid >> 2) * 64;    // 2 m-warps x 64
    const int n0 = (wid & 3) * 32;     // 4 n-warps x 32
    const int dbase = blockIdx.x * 128;
    const int h     = blockIdx.y;
    const int s     = blockIdx.z;      // 0..11

    // ldmatrix lane-address components
    const int la_row = (lane & 7) + ((lane >> 3) & 1) * 8;  // A: tiles (r,k),(r+8,k),(r,k+8),(r+8,k+8)
    const int la_col = (lane >> 4) * 8;
    const int lb_row = (lane & 7) + (lane >> 4) * 8;        // B: (n,k),(n,k+8),(n+8,k),(n+8,k+8)
    const int lb_col = ((lane >> 3) & 1) * 8;

    // stage B once
#pragma unroll
    for (int i = 0; i < 6; i++) {
        int idx = i * T2 + tid;
        int row = idx / 12, q = idx % 12;
        cpasync16(sbase + (uint32_t)(row * SA2 + q * 8) * 2,
                  &g_loth[((size_t)h * D_OUTD + dbase + row) * NCOL + q * 8]);
    }
    k2_stageA(sbase + BS2H * 2, s * 128, tid);
    asm volatile("cp.async.commit_group;" ::: "memory");

    int it = 0;
    for (int mt = s; mt < 64; mt += 12, it++) {
        const int buf = it & 1;
        __syncthreads();
        if (mt + 12 < 64) {
            k2_stageA(sbase + (BS2H + (buf ^ 1) * AS2H) * 2, (mt + 12) * 128, tid);
            asm volatile("cp.async.commit_group;" ::: "memory");
            asm volatile("cp.async.wait_group 1;" ::: "memory");
        } else {
            asm volatile("cp.async.wait_group 0;" ::: "memory");
        }
        __syncthreads();

        const uint32_t Ab = sbase + (uint32_t)(BS2H + buf * AS2H) * 2;

        float acc[4][4][4];
#pragma unroll
        for (int tm = 0; tm < 4; tm++)
#pragma unroll
            for (int tn = 0; tn < 4; tn++)
#pragma unroll
                for (int q = 0; q < 4; q++) acc[tm][tn][q] = 0.f;

#pragma unroll
        for (int ks = 0; ks < 6; ks++) {
            const int k0h = ks * 16;
            uint32_t a[4][4], b[4][2];
#pragma unroll
            for (int tm = 0; tm < 4; tm++) {
                uint32_t ad = Ab + (uint32_t)((m0 + tm * 16 + la_row) * SA2 + k0h + la_col) * 2;
                LDMX4(a[tm][0], a[tm][1], a[tm][2], a[tm][3], ad);
            }
#pragma unroll
            for (int tp = 0; tp < 2; tp++) {
                uint32_t bd = sbase + (uint32_t)((n0 + tp * 16 + lb_row) * SA2 + k0h + lb_col) * 2;
                LDMX4(b[2 * tp][0], b[2 * tp][1], b[2 * tp + 1][0], b[2 * tp + 1][1], bd);
            }
#pragma unroll
            for (int tm = 0; tm < 4; tm++)
#pragma unroll
                for (int tn = 0; tn < 4; tn++)
                    MMA_F16(acc[tm][tn], a[tm], b[tn]);
        }

        // epilogue
        const int tokbase = mt * 128;
#pragma unroll
        for (int tm = 0; tm < 4; tm++) {
            const size_t row0 = (size_t)tokbase + m0 + tm * 16 + (lane >> 2);
            float* ob = out + ((size_t)h * ntok + row0) * D_OUTD + dbase + n0 + 2 * (lane & 3);
#pragma unroll
            for (int tn = 0; tn < 4; tn++) {
                float2 v0; v0.x = acc[tm][tn][0]; v0.y = acc[tm][tn][1];
                float2 v1; v1.x = acc[tm][tn][2]; v1.y = acc[tm][tn][3];
                *(float2*)(ob + tn * 8) = v0;
                *(float2*)(ob + tn * 8 + 8 * D_OUTD) = v1;
            }
        }
    }
}

// ---------------------------------------------------------------------------
extern "C" void kernel_launch(void* const* d_in, const int* in_sizes, int n_in,
                              void* d_out, int out_size)
{
    const float* x   = (const float*)d_in[0];
    const float* dw  = (const float*)d_in[1];
    const float* db  = (const float*)d_in[2];
    const float* ntl = (const float*)d_in[3];
    const float* lo  = (const float*)d_in[4];
    const float* gw  = (const float*)d_in[5];
    const float* gb  = (const float*)d_in[6];
    float* out = (float*)d_out;

    int ntok = in_sizes[0] / D_IN;   // 8192

    cudaFuncSetAttribute(k1_mma, cudaFuncAttributeMaxDynamicSharedMemorySize, SMEM1);
    cudaFuncSetAttribute(k2_mma, cudaFuncAttributeMaxDynamicSharedMemorySize, SMEM2);

    kw_split<<<NCOL, 256>>>(dw, gw);
    k0_transpose<<<dim3(D_OUTD / 32, NCOL / 32, NHEADS), dim3(32, 8)>>>(lo);
    k1_mma<<<ntok / 64, T1, SMEM1>>>(x, db, ntl, gb, ntok);

    dim3 g2(D_OUTD / 128, NHEADS, 12);
    k2_mma<<<g2, T2, SMEM2>>>(out, ntok);
}